// round 1
// baseline (speedup 1.0000x reference)
#include <cuda_runtime.h>
#include <math_constants.h>

#define C_DIM 1024
#define N_DIM 1024
#define O_DIM 2048
#define K_NN  20

// ---------------- scratch (no allocations allowed) ----------------
__device__ float g_gram[N_DIM * N_DIM];   // 4 MB: G = x^T x
__device__ float g_x2[N_DIM];             // diag(G)
__device__ int   g_idx[N_DIM * K_NN];     // top-20 neighbor indices per column
__device__ float g_h[C_DIM * N_DIM];      // 4 MB: h = (1+eps)*x + x_sum

// ---------------- Kernel 1: Gram = x^T x ----------------
// x is (C, N) row-major. G[i][j] = sum_c x[c][i]*x[c][j].
// Both operand tiles load identically (contiguous along i/j). 64x64 tile, KT=16.
__global__ __launch_bounds__(256) void gram_kernel(const float* __restrict__ x,
                                                   float* __restrict__ G) {
    __shared__ float As[16][64];
    __shared__ float Bs[16][64];

    const int lt = threadIdx.x;          // 0..255
    const int tx = lt & 15;              // 0..15
    const int ty = lt >> 4;              // 0..15
    const int i0 = blockIdx.y * 64;
    const int j0 = blockIdx.x * 64;

    const int lk = lt >> 4;              // 0..15 (k within tile)
    const int li = (lt & 15) * 4;        // 0..60

    float acc[4][4];
#pragma unroll
    for (int r = 0; r < 4; r++)
#pragma unroll
        for (int s = 0; s < 4; s++) acc[r][s] = 0.f;

    for (int k0 = 0; k0 < C_DIM; k0 += 16) {
        float4 a = *(const float4*)&x[(k0 + lk) * N_DIM + i0 + li];
        float4 b = *(const float4*)&x[(k0 + lk) * N_DIM + j0 + li];
        *(float4*)&As[lk][li] = a;
        *(float4*)&Bs[lk][li] = b;
        __syncthreads();
#pragma unroll
        for (int kk = 0; kk < 16; kk++) {
            float4 av = *(const float4*)&As[kk][ty * 4];
            float4 bv = *(const float4*)&Bs[kk][tx * 4];
            float af[4] = {av.x, av.y, av.z, av.w};
            float bf[4] = {bv.x, bv.y, bv.z, bv.w};
#pragma unroll
            for (int r = 0; r < 4; r++)
#pragma unroll
                for (int s = 0; s < 4; s++) acc[r][s] = fmaf(af[r], bf[s], acc[r][s]);
        }
        __syncthreads();
    }

#pragma unroll
    for (int r = 0; r < 4; r++) {
        int i = i0 + ty * 4 + r;
#pragma unroll
        for (int s = 0; s < 4; s++) G[i * N_DIM + j0 + tx * 4 + s] = acc[r][s];
    }
}

// ---------------- Kernel 2: extract diag ----------------
__global__ void diag_kernel(const float* __restrict__ G, float* __restrict__ x2) {
    int n = blockIdx.x * blockDim.x + threadIdx.x;
    if (n < N_DIM) x2[n] = G[n * N_DIM + n];
}

// ---------------- Kernel 3: top-20 per row ----------------
// dist[i][j] = 2*G[i][j] - x2[i] - x2[j]; jax top_k tie-break = lowest index.
__global__ __launch_bounds__(256) void topk_kernel(const float* __restrict__ G,
                                                   const float* __restrict__ x2,
                                                   int* __restrict__ idx) {
    __shared__ float d[N_DIM];
    __shared__ float sv[256];
    __shared__ int   si[256];

    const int i = blockIdx.x;
    const int t = threadIdx.x;
    const float x2i = x2[i];

    for (int j = t; j < N_DIM; j += 256)
        d[j] = 2.f * G[i * N_DIM + j] - x2i - x2[j];
    __syncthreads();

    for (int k = 0; k < K_NN; k++) {
        float bv = -CUDART_INF_F;
        int   bi = N_DIM;
#pragma unroll
        for (int u = 0; u < 4; u++) {
            int j = t + u * 256;
            float v = d[j];
            if (v > bv || (v == bv && j < bi)) { bv = v; bi = j; }
        }
        sv[t] = bv; si[t] = bi;
        __syncthreads();
        for (int s = 128; s > 0; s >>= 1) {
            if (t < s) {
                float ov = sv[t + s]; int oi = si[t + s];
                if (ov > sv[t] || (ov == sv[t] && oi < si[t])) { sv[t] = ov; si[t] = oi; }
            }
            __syncthreads();
        }
        if (t == 0) {
            idx[i * K_NN + k] = si[0];
            d[si[0]] = -CUDART_INF_F;
        }
        __syncthreads();
    }
}

// ---------------- Kernel 4: h = (1+eps)*x + neighbor-sum ----------------
// block = one channel c; x row cached in smem so gathers stay on-chip.
__global__ __launch_bounds__(256) void h_kernel(const float* __restrict__ x,
                                                const float* __restrict__ eps,
                                                const int* __restrict__ idx,
                                                float* __restrict__ h) {
    __shared__ float xr[N_DIM];
    const int c = blockIdx.x;
    const int t = threadIdx.x;

    for (int j = t; j < N_DIM; j += 256) xr[j] = x[c * N_DIM + j];
    __syncthreads();

    for (int n = t; n < N_DIM; n += 256) {
        const int* ip = &idx[n * K_NN];
        float s = 0.f;
#pragma unroll
        for (int k = 0; k < K_NN; k++) s += xr[ip[k]];
        float xn = xr[n];
        h[c * N_DIM + n] = xn + eps[c * N_DIM + n] * xn + s;
    }
}

// ---------------- Kernel 5: out = W @ h ----------------
// W (O, C) row-major (contiguous along k); h (C, N). 64x64 tile, KT=16.
__global__ __launch_bounds__(256) void out_gemm_kernel(const float* __restrict__ W,
                                                       const float* __restrict__ h,
                                                       float* __restrict__ out) {
    __shared__ float As[16][65];   // [kk][oo], padded to kill transpose-store conflicts
    __shared__ float Bs[16][64];   // [kk][nn]

    const int lt = threadIdx.x;
    const int tx = lt & 15;
    const int ty = lt >> 4;
    const int o0 = blockIdx.y * 64;
    const int n0 = blockIdx.x * 64;

    const int oo = lt >> 2;            // 0..63
    const int kq = (lt & 3) * 4;       // 0,4,8,12
    const int lk = lt >> 4;            // 0..15
    const int ln = (lt & 15) * 4;      // 0..60

    float acc[4][4];
#pragma unroll
    for (int r = 0; r < 4; r++)
#pragma unroll
        for (int s = 0; s < 4; s++) acc[r][s] = 0.f;

    for (int k0 = 0; k0 < C_DIM; k0 += 16) {
        float4 w = *(const float4*)&W[(o0 + oo) * C_DIM + k0 + kq];
        As[kq + 0][oo] = w.x;
        As[kq + 1][oo] = w.y;
        As[kq + 2][oo] = w.z;
        As[kq + 3][oo] = w.w;
        *(float4*)&Bs[lk][ln] = *(const float4*)&h[(k0 + lk) * N_DIM + n0 + ln];
        __syncthreads();
#pragma unroll
        for (int kk = 0; kk < 16; kk++) {
            float af[4];
#pragma unroll
            for (int r = 0; r < 4; r++) af[r] = As[kk][ty * 4 + r];
            float4 bv = *(const float4*)&Bs[kk][tx * 4];
            float bf[4] = {bv.x, bv.y, bv.z, bv.w};
#pragma unroll
            for (int r = 0; r < 4; r++)
#pragma unroll
                for (int s = 0; s < 4; s++) acc[r][s] = fmaf(af[r], bf[s], acc[r][s]);
        }
        __syncthreads();
    }

#pragma unroll
    for (int r = 0; r < 4; r++) {
        int o = o0 + ty * 4 + r;
#pragma unroll
        for (int s = 0; s < 4; s++) out[o * N_DIM + n0 + tx * 4 + s] = acc[r][s];
    }
}

// ---------------- launch ----------------
extern "C" void kernel_launch(void* const* d_in, const int* in_sizes, int n_in,
                              void* d_out, int out_size) {
    const float* x   = (const float*)d_in[0];   // (C, N)
    const float* W   = (const float*)d_in[1];   // (O, C, 1, 1)
    const float* eps = (const float*)d_in[2];   // (C, N, 1)
    float* out = (float*)d_out;                 // (O, N)

    float* gram; cudaGetSymbolAddress((void**)&gram, g_gram);
    float* x2;   cudaGetSymbolAddress((void**)&x2,   g_x2);
    int*   idx;  cudaGetSymbolAddress((void**)&idx,  g_idx);
    float* h;    cudaGetSymbolAddress((void**)&h,    g_h);

    gram_kernel<<<dim3(N_DIM / 64, N_DIM / 64), 256>>>(x, gram);
    diag_kernel<<<N_DIM / 256, 256>>>(gram, x2);
    topk_kernel<<<N_DIM, 256>>>(gram, x2, idx);
    h_kernel<<<C_DIM, 256>>>(x, eps, idx, h);
    out_gemm_kernel<<<dim3(N_DIM / 64, O_DIM / 64), 256>>>(W, h, out);
}

// round 2
// speedup vs baseline: 1.0008x; 1.0008x over previous
#include <cuda_runtime.h>
#include <math_constants.h>

#define C_DIM 1024
#define N_DIM 1024
#define O_DIM 2048
#define K_NN  20

// ---------------- scratch (no allocations allowed) ----------------
__device__ float g_gram[N_DIM * N_DIM];   // 4 MB: G = x^T x
__device__ float g_x2[N_DIM];             // diag(G)
__device__ int   g_idx[N_DIM * K_NN];     // top-20 neighbor indices per column
__device__ float g_h[C_DIM * N_DIM];      // 4 MB: h = (1+eps)*x + x_sum

// ---------------- Kernel 1: Gram = x^T x ----------------
// x is (C, N) row-major. G[i][j] = sum_c x[c][i]*x[c][j].
// Both operand tiles load identically (contiguous along i/j). 64x64 tile, KT=16.
__global__ __launch_bounds__(256) void gram_kernel(const float* __restrict__ x,
                                                   float* __restrict__ G) {
    __shared__ float As[16][64];
    __shared__ float Bs[16][64];

    const int lt = threadIdx.x;          // 0..255
    const int tx = lt & 15;              // 0..15
    const int ty = lt >> 4;              // 0..15
    const int i0 = blockIdx.y * 64;
    const int j0 = blockIdx.x * 64;

    const int lk = lt >> 4;              // 0..15 (k within tile)
    const int li = (lt & 15) * 4;        // 0..60

    float acc[4][4];
#pragma unroll
    for (int r = 0; r < 4; r++)
#pragma unroll
        for (int s = 0; s < 4; s++) acc[r][s] = 0.f;

    for (int k0 = 0; k0 < C_DIM; k0 += 16) {
        float4 a = *(const float4*)&x[(k0 + lk) * N_DIM + i0 + li];
        float4 b = *(const float4*)&x[(k0 + lk) * N_DIM + j0 + li];
        *(float4*)&As[lk][li] = a;
        *(float4*)&Bs[lk][li] = b;
        __syncthreads();
#pragma unroll
        for (int kk = 0; kk < 16; kk++) {
            float4 av = *(const float4*)&As[kk][ty * 4];
            float4 bv = *(const float4*)&Bs[kk][tx * 4];
            float af[4] = {av.x, av.y, av.z, av.w};
            float bf[4] = {bv.x, bv.y, bv.z, bv.w};
#pragma unroll
            for (int r = 0; r < 4; r++)
#pragma unroll
                for (int s = 0; s < 4; s++) acc[r][s] = fmaf(af[r], bf[s], acc[r][s]);
        }
        __syncthreads();
    }

#pragma unroll
    for (int r = 0; r < 4; r++) {
        int i = i0 + ty * 4 + r;
#pragma unroll
        for (int s = 0; s < 4; s++) G[i * N_DIM + j0 + tx * 4 + s] = acc[r][s];
    }
}

// ---------------- Kernel 2: extract diag ----------------
__global__ void diag_kernel(const float* __restrict__ G, float* __restrict__ x2) {
    int n = blockIdx.x * blockDim.x + threadIdx.x;
    if (n < N_DIM) x2[n] = G[n * N_DIM + n];
}

// ---------------- Kernel 3: top-20 per row ----------------
// dist[i][j] = 2*G[i][j] - x2[i] - x2[j]; jax top_k tie-break = lowest index.
__global__ __launch_bounds__(256) void topk_kernel(const float* __restrict__ G,
                                                   const float* __restrict__ x2,
                                                   int* __restrict__ idx) {
    __shared__ float d[N_DIM];
    __shared__ float sv[256];
    __shared__ int   si[256];

    const int i = blockIdx.x;
    const int t = threadIdx.x;
    const float x2i = x2[i];

    for (int j = t; j < N_DIM; j += 256)
        d[j] = 2.f * G[i * N_DIM + j] - x2i - x2[j];
    __syncthreads();

    for (int k = 0; k < K_NN; k++) {
        float bv = -CUDART_INF_F;
        int   bi = N_DIM;
#pragma unroll
        for (int u = 0; u < 4; u++) {
            int j = t + u * 256;
            float v = d[j];
            if (v > bv || (v == bv && j < bi)) { bv = v; bi = j; }
        }
        sv[t] = bv; si[t] = bi;
        __syncthreads();
        for (int s = 128; s > 0; s >>= 1) {
            if (t < s) {
                float ov = sv[t + s]; int oi = si[t + s];
                if (ov > sv[t] || (ov == sv[t] && oi < si[t])) { sv[t] = ov; si[t] = oi; }
            }
            __syncthreads();
        }
        if (t == 0) {
            idx[i * K_NN + k] = si[0];
            d[si[0]] = -CUDART_INF_F;
        }
        __syncthreads();
    }
}

// ---------------- Kernel 4: h = (1+eps)*x + neighbor-sum ----------------
// block = one channel c; x row cached in smem so gathers stay on-chip.
__global__ __launch_bounds__(256) void h_kernel(const float* __restrict__ x,
                                                const float* __restrict__ eps,
                                                const int* __restrict__ idx,
                                                float* __restrict__ h) {
    __shared__ float xr[N_DIM];
    const int c = blockIdx.x;
    const int t = threadIdx.x;

    for (int j = t; j < N_DIM; j += 256) xr[j] = x[c * N_DIM + j];
    __syncthreads();

    for (int n = t; n < N_DIM; n += 256) {
        const int* ip = &idx[n * K_NN];
        float s = 0.f;
#pragma unroll
        for (int k = 0; k < K_NN; k++) s += xr[ip[k]];
        float xn = xr[n];
        h[c * N_DIM + n] = xn + eps[c * N_DIM + n] * xn + s;
    }
}

// ---------------- Kernel 5: out = W @ h ----------------
// W (O, C) row-major (contiguous along k); h (C, N). 64x64 tile, KT=16.
__global__ __launch_bounds__(256) void out_gemm_kernel(const float* __restrict__ W,
                                                       const float* __restrict__ h,
                                                       float* __restrict__ out) {
    __shared__ float As[16][65];   // [kk][oo], padded to kill transpose-store conflicts
    __shared__ float Bs[16][64];   // [kk][nn]

    const int lt = threadIdx.x;
    const int tx = lt & 15;
    const int ty = lt >> 4;
    const int o0 = blockIdx.y * 64;
    const int n0 = blockIdx.x * 64;

    const int oo = lt >> 2;            // 0..63
    const int kq = (lt & 3) * 4;       // 0,4,8,12
    const int lk = lt >> 4;            // 0..15
    const int ln = (lt & 15) * 4;      // 0..60

    float acc[4][4];
#pragma unroll
    for (int r = 0; r < 4; r++)
#pragma unroll
        for (int s = 0; s < 4; s++) acc[r][s] = 0.f;

    for (int k0 = 0; k0 < C_DIM; k0 += 16) {
        float4 w = *(const float4*)&W[(o0 + oo) * C_DIM + k0 + kq];
        As[kq + 0][oo] = w.x;
        As[kq + 1][oo] = w.y;
        As[kq + 2][oo] = w.z;
        As[kq + 3][oo] = w.w;
        *(float4*)&Bs[lk][ln] = *(const float4*)&h[(k0 + lk) * N_DIM + n0 + ln];
        __syncthreads();
#pragma unroll
        for (int kk = 0; kk < 16; kk++) {
            float af[4];
#pragma unroll
            for (int r = 0; r < 4; r++) af[r] = As[kk][ty * 4 + r];
            float4 bv = *(const float4*)&Bs[kk][tx * 4];
            float bf[4] = {bv.x, bv.y, bv.z, bv.w};
#pragma unroll
            for (int r = 0; r < 4; r++)
#pragma unroll
                for (int s = 0; s < 4; s++) acc[r][s] = fmaf(af[r], bf[s], acc[r][s]);
        }
        __syncthreads();
    }

#pragma unroll
    for (int r = 0; r < 4; r++) {
        int o = o0 + ty * 4 + r;
#pragma unroll
        for (int s = 0; s < 4; s++) out[o * N_DIM + n0 + tx * 4 + s] = acc[r][s];
    }
}

// ---------------- launch ----------------
extern "C" void kernel_launch(void* const* d_in, const int* in_sizes, int n_in,
                              void* d_out, int out_size) {
    const float* x   = (const float*)d_in[0];   // (C, N)
    const float* W   = (const float*)d_in[1];   // (O, C, 1, 1)
    const float* eps = (const float*)d_in[2];   // (C, N, 1)
    float* out = (float*)d_out;                 // (O, N)

    float* gram; cudaGetSymbolAddress((void**)&gram, g_gram);
    float* x2;   cudaGetSymbolAddress((void**)&x2,   g_x2);
    int*   idx;  cudaGetSymbolAddress((void**)&idx,  g_idx);
    float* h;    cudaGetSymbolAddress((void**)&h,    g_h);

    gram_kernel<<<dim3(N_DIM / 64, N_DIM / 64), 256>>>(x, gram);
    diag_kernel<<<N_DIM / 256, 256>>>(gram, x2);
    topk_kernel<<<N_DIM, 256>>>(gram, x2, idx);
    h_kernel<<<C_DIM, 256>>>(x, eps, idx, h);
    out_gemm_kernel<<<dim3(N_DIM / 64, O_DIM / 64), 256>>>(W, h, out);
}